// round 16
// baseline (speedup 1.0000x reference)
#include <cuda_runtime.h>
#include <cuda_bf16.h>
#include <stdint.h>

// out[r] = relu(hs0[r] @ W1[VOCAB:] + W1[tk[r]] + b1) @ W2 + b2
// M=65536, HIDDEN=768, HS1=128. mma.sync m16n8k16 bf16, 3-term split, fp32 acc.
// ldmatrix fragment loads + cp.async W pipeline.

#define HIDDEN   768
#define VOCAB    32000
#define HS1      128
#define BM       128
#define BK       64
#define NSTAGES  (HIDDEN / BK)   // 12
#define NTHREADS 256

// ---- smem layout (bytes). Tiles use padded stride 72 bf16 = 144 B ----
#define AST      144
#define TILEB    18432                 // 128 rows * 144
#define SM_A_HI  0
#define SM_A_LO  18432
#define SM_W_HI(b) (36864 + (b) * 36864)
#define SM_W_LO(b) (36864 + (b) * 36864 + 18432)
#define SM_B1    110592
#define SM_W2    111104
#define SMEM_TOTAL 111616
// f32 stride for epilogue dump; 133 mod 32 = 5 (coprime -> conflict-free column
// reads). NOTE: r*133+c parity alternates with r, so epilogue stores MUST be
// scalar floats (an odd-r float2 store is 4-mod-8 misaligned -> trap; R12 bug).
#define ACCST    133

// Pre-split W (hi/lo bf16, [n][k] layout) — uint4-typed so the base is 16B-aligned
// (cp.async.16 traps on misaligned src; __nv_bfloat16 arrays only guarantee 2B).
__device__ uint4 gW_hi4[HS1 * HIDDEN / 8];
__device__ uint4 gW_lo4[HS1 * HIDDEN / 8];

__device__ __forceinline__ void bsplit(float x, __nv_bfloat16 &h, __nv_bfloat16 &l) {
    h = __float2bfloat16_rn(x);
    l = __float2bfloat16_rn(x - __bfloat162float(h));
}

__global__ void wsplit_kernel(const float* __restrict__ W1) {
    int i = blockIdx.x * blockDim.x + threadIdx.x;   // over HIDDEN*HS1
    if (i >= HIDDEN * HS1) return;
    int k = i >> 7, n = i & 127;
    float w = W1[(size_t)VOCAB * HS1 + (size_t)k * HS1 + n];
    __nv_bfloat16 h, l;
    bsplit(w, h, l);
    ((__nv_bfloat16*)gW_hi4)[n * HIDDEN + k] = h;
    ((__nv_bfloat16*)gW_lo4)[n * HIDDEN + k] = l;
}

__device__ __forceinline__ uint32_t smem_u32(const void* p) {
    uint32_t a;
    asm("{ .reg .u64 t; cvta.to.shared.u64 t, %1; cvt.u32.u64 %0, t; }" : "=r"(a) : "l"(p));
    return a;
}

#define LDMX4(r0, r1, r2, r3, addr) \
    asm volatile("ldmatrix.sync.aligned.m8n8.x4.shared.b16 {%0,%1,%2,%3}, [%4];" \
        : "=r"(r0), "=r"(r1), "=r"(r2), "=r"(r3) : "r"(addr))

#define CP_ASYNC16(dst, src) \
    asm volatile("cp.async.ca.shared.global [%0], [%1], 16;" :: "r"(dst), "l"(src))
#define CP_COMMIT() asm volatile("cp.async.commit_group;" ::: "memory")
#define CP_WAIT(n)  asm volatile("cp.async.wait_group %0;" :: "n"(n) : "memory")

// D += A(bf16) * B(bf16), m16n8k16, row.col, fp32 accumulate.
__device__ __forceinline__ void mma16816(float* d, const uint32_t* a, const uint32_t* b) {
    asm volatile(
        "mma.sync.aligned.m16n8k16.row.col.f32.bf16.bf16.f32 "
        "{%0,%1,%2,%3}, {%4,%5,%6,%7}, {%8,%9}, {%0,%1,%2,%3};"
        : "+f"(d[0]), "+f"(d[1]), "+f"(d[2]), "+f"(d[3])
        : "r"(a[0]), "r"(a[1]), "r"(a[2]), "r"(a[3]), "r"(b[0]), "r"(b[1]));
}

__global__ __launch_bounds__(NTHREADS)
void classifier_mma(const int* __restrict__ tk,
                    const float* __restrict__ hs0,
                    const float* __restrict__ W1,
                    const float* __restrict__ b1,
                    const float* __restrict__ W2,
                    const float* __restrict__ b2,
                    float* __restrict__ out,
                    int M)
{
    extern __shared__ char smem[];
    const uint32_t sb = smem_u32(smem);
    const int tid = threadIdx.x;
    const int wid = tid >> 5, lane = tid & 31;
    const int warp_m = wid & 3, warp_n = wid >> 2;   // 4 M-warps x 2 N-warps
    const int m0 = blockIdx.x * BM;

    if (tid < HS1) {
        *(float*)(smem + SM_B1 + tid * 4) = b1[tid];
        *(float*)(smem + SM_W2 + tid * 4) = W2[tid];
    }

    float acc[2][8][4];
    #pragma unroll
    for (int mt = 0; mt < 2; mt++)
        #pragma unroll
        for (int nt = 0; nt < 8; nt++)
            #pragma unroll
            for (int v = 0; v < 4; v++) acc[mt][nt][v] = 0.f;

    // A prefetch registers: 32 floats (8 float4) per thread
    float4 pa[4][2];
    const int a_row = tid >> 3;                // base row (stride 32 over u)
    const int a_seg = tid & 7;

    const __nv_bfloat16* gWh = (const __nv_bfloat16*)gW_hi4;
    const __nv_bfloat16* gWl = (const __nv_bfloat16*)gW_lo4;

    // W cp.async mapping: 8 chunks of 16B per thread per stage
    // e = tid + u*256; half = e>>10 (0=hi), n = (e&1023)>>3, chunk = e&7
    auto issue_w = [&](int s, int buf) {
        const int k0 = s * BK;
        #pragma unroll
        for (int u = 0; u < 8; u++) {
            int e = tid + u * 256;
            int half = e >> 10, r = (e & 1023) >> 3, ch = e & 7;
            uint32_t dst = sb + (half ? SM_W_LO(buf) : SM_W_HI(buf)) + r * AST + ch * 16;
            const __nv_bfloat16* src = (half ? gWl : gWh) + (size_t)r * HIDDEN + k0 + ch * 8;
            CP_ASYNC16(dst, src);
        }
        CP_COMMIT();
    };

    auto ldg_a = [&](int s) {
        const int k0 = s * BK;
        #pragma unroll
        for (int u = 0; u < 4; u++) {
            int row = a_row + u * 32;
            int r = m0 + row; if (r >= M) r = M - 1;
            const float4* p = (const float4*)&hs0[(size_t)r * HIDDEN + k0 + a_seg * 8];
            pa[u][0] = p[0]; pa[u][1] = p[1];
        }
    };
    auto sts_a = [&]() {
        #pragma unroll
        for (int u = 0; u < 4; u++) {
            int row = a_row + u * 32;
            float f[8] = {pa[u][0].x, pa[u][0].y, pa[u][0].z, pa[u][0].w,
                          pa[u][1].x, pa[u][1].y, pa[u][1].z, pa[u][1].w};
            __nv_bfloat162 hi2[4], lo2[4];
            #pragma unroll
            for (int j = 0; j < 4; j++) {
                __nv_bfloat16 h0, l0, h1, l1;
                bsplit(f[2 * j], h0, l0); bsplit(f[2 * j + 1], h1, l1);
                hi2[j] = __halves2bfloat162(h0, h1);
                lo2[j] = __halves2bfloat162(l0, l1);
            }
            uint32_t base = row * AST + a_seg * 16;
            *(uint4*)(smem + SM_A_HI + base) = *(uint4*)hi2;
            *(uint4*)(smem + SM_A_LO + base) = *(uint4*)lo2;
        }
    };

    // ---- prologue ----
    issue_w(0, 0);
    issue_w(1, 1);
    ldg_a(0);
    sts_a();
    CP_WAIT(1);          // W(0) resident
    __syncthreads();

    // ldmatrix lane addressing (shared by A and B; group = lane>>3)
    const int grp = lane >> 3, lrow = lane & 7;
    const uint32_t a_base = (uint32_t)((warp_m * 32 + (grp & 1) * 8 + lrow) * AST + (grp >> 1) * 16);
    const uint32_t b_base = (uint32_t)((warp_n * 64 + (grp & 1) * 8 + lrow) * AST + (grp >> 1) * 16);

    // ---- main loop ----
    for (int s = 0; s < NSTAGES; s++) {
        const int wb = s & 1;
        if (s + 1 < NSTAGES) ldg_a(s + 1);   // LDG latency hides under compute

        #pragma unroll
        for (int kk = 0; kk < 4; kk++) {
            const uint32_t ko = kk * 32;
            uint32_t ah[2][4], al[2][4];
            #pragma unroll
            for (int mt = 0; mt < 2; mt++) {
                uint32_t ao = a_base + mt * 16 * AST + ko;
                LDMX4(ah[mt][0], ah[mt][1], ah[mt][2], ah[mt][3], sb + SM_A_HI + ao);
                LDMX4(al[mt][0], al[mt][1], al[mt][2], al[mt][3], sb + SM_A_LO + ao);
            }
            uint32_t bh[8][2], bl[8][2];
            #pragma unroll
            for (int c = 0; c < 4; c++) {
                uint32_t bo = b_base + c * 16 * AST + ko;
                uint32_t r0, r1, r2, r3;
                LDMX4(r0, r1, r2, r3, sb + SM_W_HI(wb) + bo);
                bh[2 * c][0] = r0; bh[2 * c][1] = r2;
                bh[2 * c + 1][0] = r1; bh[2 * c + 1][1] = r3;
                LDMX4(r0, r1, r2, r3, sb + SM_W_LO(wb) + bo);
                bl[2 * c][0] = r0; bl[2 * c][1] = r2;
                bl[2 * c + 1][0] = r1; bl[2 * c + 1][1] = r3;
            }
            #pragma unroll
            for (int mt = 0; mt < 2; mt++)
                #pragma unroll
                for (int nt = 0; nt < 8; nt++) {
                    mma16816(acc[mt][nt], ah[mt], bh[nt]);   // hi*hi
                    mma16816(acc[mt][nt], ah[mt], bl[nt]);   // hi*lo
                    mma16816(acc[mt][nt], al[mt], bh[nt]);   // lo*hi
                }
        }

        if (s + 1 < NSTAGES) {
            __syncthreads();                  // A smem + W buf free
            sts_a();                          // A(s+1)
            if (s + 2 < NSTAGES) { issue_w(s + 2, wb); CP_WAIT(1); }
            else                 { CP_WAIT(0); }
            __syncthreads();
        }
    }

    // ---- epilogue: dump acc to smem (f32, stride 133, SCALAR stores), fuse ----
    __syncthreads();
    float* accb = (float*)smem;
    const int g = lane >> 2, tg = lane & 3;
    #pragma unroll
    for (int mt = 0; mt < 2; mt++)
        #pragma unroll
        for (int nt = 0; nt < 8; nt++) {
            int r = warp_m * 32 + mt * 16 + g;
            int c = warp_n * 64 + nt * 8 + tg * 2;
            accb[r * ACCST + c]           = acc[mt][nt][0];
            accb[r * ACCST + c + 1]       = acc[mt][nt][1];
            accb[(r + 8) * ACCST + c]     = acc[mt][nt][2];
            accb[(r + 8) * ACCST + c + 1] = acc[mt][nt][3];
        }
    __syncthreads();

    if (tid < BM) {
        int row = m0 + tid;
        if (row < M) {
            unsigned t = (unsigned)tk[row];
            if (t >= VOCAB) t = 0;
            const float* wt  = W1 + (size_t)t * HS1;
            const float* b1s = (const float*)(smem + SM_B1);
            const float* w2s = (const float*)(smem + SM_W2);
            float s = 0.f;
            #pragma unroll 16
            for (int col = 0; col < HS1; col++) {
                float h = accb[tid * ACCST + col] + wt[col] + b1s[col];
                s += fmaxf(h, 0.f) * w2s[col];
            }
            out[row] = s + b2[0];
        }
    }
}

extern "C" void kernel_launch(void* const* d_in, const int* in_sizes, int n_in,
                              void* d_out, int out_size) {
    const int*   tk  = (const int*)d_in[0];
    const float* hs0 = (const float*)d_in[1];
    const float* W1  = (const float*)d_in[2];
    const float* b1  = (const float*)d_in[3];
    const float* W2  = (const float*)d_in[4];
    const float* b2  = (const float*)d_in[5];
    float* out = (float*)d_out;

    int M = in_sizes[0];                          // 65536
    int grid = (M + BM - 1) / BM;                 // 512

    wsplit_kernel<<<(HIDDEN * HS1 + 255) / 256, 256>>>(W1);
    cudaFuncSetAttribute(classifier_mma, cudaFuncAttributeMaxDynamicSharedMemorySize, SMEM_TOTAL);
    classifier_mma<<<grid, NTHREADS, SMEM_TOTAL>>>(tk, hs0, W1, b1, W2, b2, out, M);
}